// round 9
// baseline (speedup 1.0000x reference)
#include <cuda_runtime.h>
#include <cstdint>
#include <math.h>

#define B_ 16
#define T_ 2048
#define C_ 1024
#define H_ 64
#define ROWS_ (B_ * T_)   // 32768

// Scratch for projected q, k, v (fp32)
__device__ float g_q[ROWS_ * H_];
__device__ float g_k[ROWS_ * H_];
__device__ float g_v[ROWS_ * H_];

// log2(e) / sqrt(H) folded into q so attention uses exp2f directly
#define QSCALE 0.18033688011112042f   // 1.4426950408889634f * 0.125f

// ---------------------------------------------------------------------------
// Packed f32x2 helpers (Blackwell: 2 fp32 FMAs per issue slot)
// ---------------------------------------------------------------------------
typedef unsigned long long u64_t;

__device__ __forceinline__ u64_t pack2(float lo, float hi) {
    u64_t o;
    asm("mov.b64 %0, {%1, %2};" : "=l"(o)
        : "r"(__float_as_uint(lo)), "r"(__float_as_uint(hi)));
    return o;
}
__device__ __forceinline__ u64_t bcast2(float v) { return pack2(v, v); }
__device__ __forceinline__ void fma2(u64_t& d, u64_t a, u64_t b) {
    asm("fma.rn.f32x2 %0, %1, %2, %0;" : "+l"(d) : "l"(a), "l"(b));
}
__device__ __forceinline__ void mul2(u64_t& d, u64_t a) {
    asm("mul.rn.f32x2 %0, %0, %1;" : "+l"(d) : "l"(a));
}
__device__ __forceinline__ float2 unpk(u64_t p) {
    unsigned lo, hi;
    asm("mov.b64 {%0, %1}, %2;" : "=r"(lo), "=r"(hi) : "l"(p));
    return make_float2(__uint_as_float(lo), __uint_as_float(hi));
}

// ---------------------------------------------------------------------------
// Kernel 1: QKV projection (SIMT f32x2).  BM=128, BN=64, BK=32, 256 threads.
// As stored transposed [k][m] -> m-pairs are contiguous 64-bit halves.
// Thread tile: 4 m-pairs (8 rows) x 4 n.
// ---------------------------------------------------------------------------
__global__ __launch_bounds__(256, 3)
void qkv_proj_kernel(const float* __restrict__ x,
                     const float* __restrict__ wq,
                     const float* __restrict__ wk,
                     const float* __restrict__ wv)
{
    __shared__ float As[32][132];   // A^T tile (pad 132)
    __shared__ float Bs[32][64];

    const int which = blockIdx.y;
    const float* __restrict__ w = (which == 0) ? wq : (which == 1) ? wk : wv;
    float* __restrict__ outp     = (which == 0) ? g_q : (which == 1) ? g_k : g_v;

    const int rowBase = blockIdx.x * 128;
    const int tid = threadIdx.x;
    const int tx  = tid & 15;   // n group: cols 4*tx..
    const int ty  = tid >> 4;   // m group: rows 8*ty..

    u64_t acc2[4][4];           // [m-pair][n]
#pragma unroll
    for (int mp = 0; mp < 4; mp++)
#pragma unroll
        for (int n = 0; n < 4; n++) acc2[mp][n] = 0ULL;

    for (int kt = 0; kt < C_; kt += 32) {
        // --- load A tile (128 rows x 32 k), store transposed ---
#pragma unroll
        for (int it = 0; it < 4; it++) {
            int f4 = tid + it * 256;
            int r  = f4 >> 3;       // 0..127
            int c4 = f4 & 7;        // 0..7
            float4 v = *(const float4*)&x[(size_t)(rowBase + r) * C_ + kt + c4 * 4];
            As[c4 * 4 + 0][r] = v.x;
            As[c4 * 4 + 1][r] = v.y;
            As[c4 * 4 + 2][r] = v.z;
            As[c4 * 4 + 3][r] = v.w;
        }
        // --- load B tile (32 k x 64 n) ---
#pragma unroll
        for (int it = 0; it < 2; it++) {
            int f4 = tid + it * 256;
            int kr = f4 >> 4;       // 0..31
            int c4 = f4 & 15;       // 0..15
            *(float4*)&Bs[kr][c4 * 4] =
                *(const float4*)&w[(size_t)(kt + kr) * H_ + c4 * 4];
        }
        __syncthreads();

#pragma unroll 4
        for (int k = 0; k < 32; k++) {
            ulonglong2 a01 = *(const ulonglong2*)&As[k][ty * 8];      // pairs (m0m1,m2m3)
            ulonglong2 a23 = *(const ulonglong2*)&As[k][ty * 8 + 4];  // pairs (m4m5,m6m7)
            float4 b = *(const float4*)&Bs[k][tx * 4];
            u64_t b0 = bcast2(b.x), b1 = bcast2(b.y), b2 = bcast2(b.z), b3 = bcast2(b.w);
            fma2(acc2[0][0], a01.x, b0); fma2(acc2[0][1], a01.x, b1);
            fma2(acc2[0][2], a01.x, b2); fma2(acc2[0][3], a01.x, b3);
            fma2(acc2[1][0], a01.y, b0); fma2(acc2[1][1], a01.y, b1);
            fma2(acc2[1][2], a01.y, b2); fma2(acc2[1][3], a01.y, b3);
            fma2(acc2[2][0], a23.x, b0); fma2(acc2[2][1], a23.x, b1);
            fma2(acc2[2][2], a23.x, b2); fma2(acc2[2][3], a23.x, b3);
            fma2(acc2[3][0], a23.y, b0); fma2(acc2[3][1], a23.y, b1);
            fma2(acc2[3][2], a23.y, b2); fma2(acc2[3][3], a23.y, b3);
        }
        __syncthreads();
    }

    const float s = (which == 0) ? QSCALE : 1.0f;
#pragma unroll
    for (int mp = 0; mp < 4; mp++) {
        float2 c0 = unpk(acc2[mp][0]);
        float2 c1 = unpk(acc2[mp][1]);
        float2 c2 = unpk(acc2[mp][2]);
        float2 c3 = unpk(acc2[mp][3]);
        float4 r0 = { c0.x * s, c1.x * s, c2.x * s, c3.x * s };
        float4 r1 = { c0.y * s, c1.y * s, c2.y * s, c3.y * s };
        *(float4*)&outp[(size_t)(rowBase + ty * 8 + 2 * mp)     * H_ + tx * 4] = r0;
        *(float4*)&outp[(size_t)(rowBase + ty * 8 + 2 * mp + 1) * H_ + tx * 4] = r1;
    }
}

// ---------------------------------------------------------------------------
// Kernel 2: causal flash attention, f32x2.  BQ = BKV = 64, 128 threads.
// Q staged transposed (stride 68) -> S-GEMM m-pairs contiguous.
// O-GEMM c-paired: V float4 = two natural c-pairs; P broadcast packs.
// P in its own buffer with row-XOR col swizzle (fixes 8/16-way conflicts).
// ---------------------------------------------------------------------------
#define QT_STRIDE 68
#define KS_OFF 17408
#define VS_OFF 33792
#define PS_OFF 50176
#define ATTN_SMEM 66560

__global__ __launch_bounds__(128, 3)
void attn_kernel(float* __restrict__ out)
{
    extern __shared__ char smem_raw[];
    float* Qt = (float*)(smem_raw);            // [h][m] stride 68
    float* Ks = (float*)(smem_raw + KS_OFF);   // [r][c] stride 64, col ^= r>>2
    float* Vs = (float*)(smem_raw + VS_OFF);   // [r][c] stride 64
    float* Ps = (float*)(smem_raw + PS_OFF);   // [r][c] stride 64, col ^= r>>2

    const int tid = threadIdx.x;
    const int j = tid & 15;    // kv-col group (S) / h-col group (O)
    const int i = tid >> 4;    // q-row group (rows 8i..8i+7)

    const int b = blockIdx.x >> 4;
    const int p = blockIdx.x & 15;
    const size_t bRow = (size_t)b * T_;

    for (int half = 0; half < 2; half++) {
        const int qt = (half == 0) ? p : (31 - p);
        const int qBase = qt * 64;

        // load Q tile transposed: Qt[col][row]
#pragma unroll
        for (int it = 0; it < 8; it++) {
            int f4 = tid + it * 128;
            int r = f4 >> 4, c = f4 & 15;
            float4 v = *(const float4*)&g_q[(bRow + qBase + r) * H_ + c * 4];
            Qt[(4 * c + 0) * QT_STRIDE + r] = v.x;
            Qt[(4 * c + 1) * QT_STRIDE + r] = v.y;
            Qt[(4 * c + 2) * QT_STRIDE + r] = v.z;
            Qt[(4 * c + 3) * QT_STRIDE + r] = v.w;
        }

        float m_i[8], l_i[8];
        u64_t acc2[8][2];
#pragma unroll
        for (int m = 0; m < 8; m++) {
            m_i[m] = -1e30f; l_i[m] = 0.0f;
            acc2[m][0] = 0ULL; acc2[m][1] = 0ULL;
        }

        for (int kt = 0; kt <= qt; kt++) {
            const int kvBase = kt * 64;
            // stage K (swizzled) and V
#pragma unroll
            for (int it = 0; it < 8; it++) {
                int f4 = tid + it * 128;
                int r = f4 >> 4, c = f4 & 15;
                int cp = c ^ (r >> 2);
                *(float4*)&Ks[r * 64 + cp * 4] =
                    *(const float4*)&g_k[(bRow + kvBase + r) * H_ + c * 4];
                *(float4*)&Vs[r * 64 + c * 4] =
                    *(const float4*)&g_v[(bRow + kvBase + r) * H_ + c * 4];
            }
            __syncthreads();

            // ---- S = Q K^T, m-paired:  S2[mp][n] = rows (8i+2mp, 8i+2mp+1) ----
            u64_t S2[4][4];
#pragma unroll
            for (int mp = 0; mp < 4; mp++)
#pragma unroll
                for (int n = 0; n < 4; n++) S2[mp][n] = 0ULL;

#pragma unroll 4
            for (int h4 = 0; h4 < 16; h4++) {
                float kfa[4][4];
#pragma unroll
                for (int n = 0; n < 4; n++) {
                    float4 kf = *(const float4*)&Ks[(4 * j + n) * 64 + 4 * (h4 ^ j)];
                    kfa[n][0] = kf.x; kfa[n][1] = kf.y; kfa[n][2] = kf.z; kfa[n][3] = kf.w;
                }
#pragma unroll
                for (int u = 0; u < 4; u++) {
                    const float* qrow = Qt + (4 * h4 + u) * QT_STRIDE + 8 * i;
                    ulonglong2 q01 = *(const ulonglong2*)qrow;
                    ulonglong2 q23 = *(const ulonglong2*)(qrow + 4);
#pragma unroll
                    for (int n = 0; n < 4; n++) {
                        u64_t bb = bcast2(kfa[n][u]);
                        fma2(S2[0][n], q01.x, bb);
                        fma2(S2[1][n], q01.y, bb);
                        fma2(S2[2][n], q23.x, bb);
                        fma2(S2[3][n], q23.y, bb);
                    }
                }
            }

            // unpack S2 -> S[m][n]  (row 8i+m)
            float S[8][4];
#pragma unroll
            for (int mp = 0; mp < 4; mp++)
#pragma unroll
                for (int n = 0; n < 4; n++) {
                    float2 t = unpk(S2[mp][n]);
                    S[2 * mp][n]     = t.x;
                    S[2 * mp + 1][n] = t.y;
                }

            // causal mask on the diagonal tile
            if (kt == qt) {
#pragma unroll
                for (int m = 0; m < 8; m++)
#pragma unroll
                    for (int n = 0; n < 4; n++)
                        if (4 * j + n > 8 * i + m) S[m][n] = -1e30f;
            }

            // ---- online softmax; write P into Ps (swizzled) ----
#pragma unroll
            for (int m = 0; m < 8; m++) {
                float rmax = fmaxf(fmaxf(S[m][0], S[m][1]), fmaxf(S[m][2], S[m][3]));
#pragma unroll
                for (int msk = 8; msk >= 1; msk >>= 1)
                    rmax = fmaxf(rmax, __shfl_xor_sync(0xffffffffu, rmax, msk));
                float mNew = fmaxf(m_i[m], rmax);
                float factor = exp2f(m_i[m] - mNew);
                float4 pv;
                pv.x = exp2f(S[m][0] - mNew);
                pv.y = exp2f(S[m][1] - mNew);
                pv.z = exp2f(S[m][2] - mNew);
                pv.w = exp2f(S[m][3] - mNew);
                float rsum = pv.x + pv.y + pv.z + pv.w;
#pragma unroll
                for (int msk = 8; msk >= 1; msk >>= 1)
                    rsum += __shfl_xor_sync(0xffffffffu, rsum, msk);
                l_i[m] = l_i[m] * factor + rsum;
                m_i[m] = mNew;
                u64_t f2b = bcast2(factor);
                mul2(acc2[m][0], f2b);
                mul2(acc2[m][1], f2b);
                int row = 8 * i + m;
                *(float4*)&Ps[row * 64 + 4 * (j ^ (row >> 2))] = pv;
            }
            __syncthreads();   // P visible to all threads

            // ---- O += P V, c-paired: acc2[m] = col pairs (4j,4j+1),(4j+2,4j+3) ----
#pragma unroll 4
            for (int kv4 = 0; kv4 < 16; kv4++) {
                ulonglong2 vp[4];
#pragma unroll
                for (int n = 0; n < 4; n++)
                    vp[n] = *(const ulonglong2*)&Vs[(4 * kv4 + n) * 64 + 4 * j];
#pragma unroll
                for (int m = 0; m < 8; m++) {
                    int row = 8 * i + m;
                    float4 pm = *(const float4*)&Ps[row * 64 + 4 * (kv4 ^ (row >> 2))];
                    u64_t p0 = bcast2(pm.x), p1 = bcast2(pm.y);
                    u64_t p2 = bcast2(pm.z), p3 = bcast2(pm.w);
                    fma2(acc2[m][0], p0, vp[0].x); fma2(acc2[m][1], p0, vp[0].y);
                    fma2(acc2[m][0], p1, vp[1].x); fma2(acc2[m][1], p1, vp[1].y);
                    fma2(acc2[m][0], p2, vp[2].x); fma2(acc2[m][1], p2, vp[2].y);
                    fma2(acc2[m][0], p3, vp[3].x); fma2(acc2[m][1], p3, vp[3].y);
                }
            }
            __syncthreads();   // O-GEMM done before next tile overwrites Ks/Vs/Ps
        }

        // epilogue: normalize and store
#pragma unroll
        for (int m = 0; m < 8; m++) {
            float inv = 1.0f / l_i[m];
            float2 c01 = unpk(acc2[m][0]);
            float2 c23 = unpk(acc2[m][1]);
            float4 o = { c01.x * inv, c01.y * inv, c23.x * inv, c23.y * inv };
            *(float4*)&out[(bRow + qBase + 8 * i + m) * H_ + 4 * j] = o;
        }
        __syncthreads();   // safe before next half restages Qt
    }
}

// ---------------------------------------------------------------------------
extern "C" void kernel_launch(void* const* d_in, const int* in_sizes, int n_in,
                              void* d_out, int out_size)
{
    const float* x  = (const float*)d_in[0];
    const float* wq = (const float*)d_in[1];
    const float* wk = (const float*)d_in[2];
    const float* wv = (const float*)d_in[3];
    float* out = (float*)d_out;

    cudaFuncSetAttribute(attn_kernel,
                         cudaFuncAttributeMaxDynamicSharedMemorySize, ATTN_SMEM);

    dim3 gProj(ROWS_ / 128, 3);
    qkv_proj_kernel<<<gProj, 256>>>(x, wq, wk, wv);
    attn_kernel<<<B_ * 16, 128, ATTN_SMEM>>>(out);
}

// round 10
// speedup vs baseline: 1.7894x; 1.7894x over previous
#include <cuda_runtime.h>
#include <cstdint>
#include <math.h>

#define B_ 16
#define T_ 2048
#define C_ 1024
#define H_ 64
#define ROWS_ (B_ * T_)   // 32768

// Scratch for projected q, k, v (fp32)
__device__ float g_q[ROWS_ * H_];
__device__ float g_k[ROWS_ * H_];
__device__ float g_v[ROWS_ * H_];

// log2(e) / sqrt(H) folded into q so attention uses exp2f directly
#define QSCALE 0.18033688011112042f   // 1.4426950408889634f * 0.125f

__device__ __forceinline__ uint32_t smem_u32(const void* p) {
    uint32_t a;
    asm("{ .reg .u64 t; cvta.to.shared.u64 t, %1; cvt.u32.u64 %0, t; }"
        : "=r"(a) : "l"(p));
    return a;
}
__device__ __forceinline__ void cp16(uint32_t dst, const void* src) {
    asm volatile("cp.async.ca.shared.global [%0], [%1], 16;"
                 :: "r"(dst), "l"(src) : "memory");
}
#define CP_COMMIT() asm volatile("cp.async.commit_group;" ::: "memory")
#define CP_WAIT0()  asm volatile("cp.async.wait_group 0;" ::: "memory")

// ---------------------------------------------------------------------------
// Kernel 1: QKV projection.  BM=128, BN=64, BK=32, 256 threads, 8x4 regs.
// Register double-buffer: LDG for tile kt+32 issued right after the sync,
// consumed next iteration -> global latency hidden under 32 k-steps of FFMA.
// ---------------------------------------------------------------------------
__global__ __launch_bounds__(256, 2)
void qkv_proj_kernel(const float* __restrict__ x,
                     const float* __restrict__ wq,
                     const float* __restrict__ wk,
                     const float* __restrict__ wv)
{
    __shared__ float As[32][132];   // A^T tile (pad 132)
    __shared__ float Bs[32][64];

    const int which = blockIdx.y;
    const float* __restrict__ w = (which == 0) ? wq : (which == 1) ? wk : wv;
    float* __restrict__ outp     = (which == 0) ? g_q : (which == 1) ? g_k : g_v;

    const int rowBase = blockIdx.x * 128;
    const int tid = threadIdx.x;
    const int tx  = tid & 15;   // n group: cols 4*tx..
    const int ty  = tid >> 4;   // m group: rows 8*ty..

    float acc[8][4];
#pragma unroll
    for (int m = 0; m < 8; m++)
#pragma unroll
        for (int n = 0; n < 4; n++) acc[m][n] = 0.0f;

    // prologue: load tile kt=0 into registers
    float4 aR[4], bR[2];
#pragma unroll
    for (int it = 0; it < 4; it++) {
        int f4 = tid + it * 256;
        int r = f4 >> 3, c4 = f4 & 7;
        aR[it] = *(const float4*)&x[(size_t)(rowBase + r) * C_ + c4 * 4];
    }
#pragma unroll
    for (int it = 0; it < 2; it++) {
        int f4 = tid + it * 256;
        int kr = f4 >> 4, c4 = f4 & 15;
        bR[it] = *(const float4*)&w[(size_t)kr * H_ + c4 * 4];
    }

    for (int kt = 0; kt < C_; kt += 32) {
        // ---- store staged registers into smem (A transposed) ----
#pragma unroll
        for (int it = 0; it < 4; it++) {
            int f4 = tid + it * 256;
            int r = f4 >> 3, c4 = f4 & 7;
            As[c4 * 4 + 0][r] = aR[it].x;
            As[c4 * 4 + 1][r] = aR[it].y;
            As[c4 * 4 + 2][r] = aR[it].z;
            As[c4 * 4 + 3][r] = aR[it].w;
        }
#pragma unroll
        for (int it = 0; it < 2; it++) {
            int f4 = tid + it * 256;
            int kr = f4 >> 4, c4 = f4 & 15;
            *(float4*)&Bs[kr][c4 * 4] = bR[it];
        }
        __syncthreads();

        // ---- prefetch next tile into registers (hidden under compute) ----
        if (kt + 32 < C_) {
#pragma unroll
            for (int it = 0; it < 4; it++) {
                int f4 = tid + it * 256;
                int r = f4 >> 3, c4 = f4 & 7;
                aR[it] = *(const float4*)&x[(size_t)(rowBase + r) * C_ + kt + 32 + c4 * 4];
            }
#pragma unroll
            for (int it = 0; it < 2; it++) {
                int f4 = tid + it * 256;
                int kr = f4 >> 4, c4 = f4 & 15;
                bR[it] = *(const float4*)&w[(size_t)(kt + 32 + kr) * H_ + c4 * 4];
            }
        }

        // ---- compute ----
#pragma unroll 8
        for (int k = 0; k < 32; k++) {
            float4 b0 = *(const float4*)&Bs[k][tx * 4];
            float4 a0 = *(const float4*)&As[k][ty * 8];
            float4 a1 = *(const float4*)&As[k][ty * 8 + 4];
            float av[8] = {a0.x, a0.y, a0.z, a0.w, a1.x, a1.y, a1.z, a1.w};
            float bv[4] = {b0.x, b0.y, b0.z, b0.w};
#pragma unroll
            for (int m = 0; m < 8; m++)
#pragma unroll
                for (int n = 0; n < 4; n++)
                    acc[m][n] += av[m] * bv[n];
        }
        __syncthreads();
    }

    const float s = (which == 0) ? QSCALE : 1.0f;
#pragma unroll
    for (int m = 0; m < 8; m++) {
        float4 o;
        o.x = acc[m][0] * s; o.y = acc[m][1] * s;
        o.z = acc[m][2] * s; o.w = acc[m][3] * s;
        *(float4*)&outp[(size_t)(rowBase + ty * 8 + m) * H_ + tx * 4] = o;
    }
}

// ---------------------------------------------------------------------------
// Kernel 2: causal flash attention.  BQ = BKV = 64, 128 threads.
// One q-tile per block (512 blocks, heaviest first).  K/V double-buffered
// via cp.async (prefetch tile t+1 under tile t compute).  P aliases the
// CURRENT K buffer (disjoint from in-flight prefetch buffer).  3 syncs/tile.
// ---------------------------------------------------------------------------
#define ATTN_SMEM 81920   // Q 16K | K0 16K | K1 16K | V0 16K | V1 16K

__global__ __launch_bounds__(128, 2)
void attn_kernel(float* __restrict__ out)
{
    extern __shared__ char sm[];
    float* Qs = (float*)sm;                         // [64][64]
    const uint32_t smBase = smem_u32(sm);

    const int tid = threadIdx.x;
    const int j = tid & 15;    // kv-col group (S) / h-col group (O)
    const int i = tid >> 4;    // q-row group (rows 8i..8i+7)

    const int b  = blockIdx.x & 15;
    const int qt = 31 - (blockIdx.x >> 4);   // heaviest q-tiles first
    const size_t bRow = (size_t)b * T_;
    const int qBase = qt * 64;

    // per-thread staging coords (8 vectors of 16B each for K and V)
    // f4 = tid + it*128 -> r = f4>>4, c = f4&15

    // ---- load Q tile (plain) ----
#pragma unroll
    for (int it = 0; it < 8; it++) {
        int f4 = tid + it * 128;
        int r = f4 >> 4, c = f4 & 15;
        *(float4*)&Qs[r * 64 + c * 4] =
            *(const float4*)&g_q[(bRow + qBase + r) * H_ + c * 4];
    }

    // ---- prologue: cp.async stage kv-tile 0 into buffer 0 ----
    {
        const uint32_t kB = smBase + 16384;
        const uint32_t vB = smBase + 49152;
#pragma unroll
        for (int it = 0; it < 8; it++) {
            int f4 = tid + it * 128;
            int r = f4 >> 4, c = f4 & 15;
            cp16(kB + 4 * (r * 64 + 4 * (c ^ (r >> 2))),
                 &g_k[(bRow + r) * H_ + c * 4]);
            cp16(vB + 4 * (r * 64 + 4 * c),
                 &g_v[(bRow + r) * H_ + c * 4]);
        }
        CP_COMMIT();
    }

    float m_i[8], l_i[8], acc[8][4];
#pragma unroll
    for (int m = 0; m < 8; m++) {
        m_i[m] = -1e30f; l_i[m] = 0.0f;
#pragma unroll
        for (int n = 0; n < 4; n++) acc[m][n] = 0.0f;
    }

    for (int kt = 0; kt <= qt; kt++) {
        const int cur = kt & 1;
        float* Ks = (float*)(sm + 16384 + cur * 16384);
        float* Vs = (float*)(sm + 49152 + cur * 16384);
        float* Ps = Ks;   // P overwrites current K after S-GEMM

        CP_WAIT0();
        __syncthreads();   // tile kt data visible; prior iteration fully done

        // ---- prefetch kv-tile kt+1 into the other buffer ----
        if (kt < qt) {
            const int nxtBase = (kt + 1) * 64;
            const uint32_t kB = smBase + 16384 + (cur ^ 1) * 16384;
            const uint32_t vB = smBase + 49152 + (cur ^ 1) * 16384;
#pragma unroll
            for (int it = 0; it < 8; it++) {
                int f4 = tid + it * 128;
                int r = f4 >> 4, c = f4 & 15;
                cp16(kB + 4 * (r * 64 + 4 * (c ^ (r >> 2))),
                     &g_k[(bRow + nxtBase + r) * H_ + c * 4]);
                cp16(vB + 4 * (r * 64 + 4 * c),
                     &g_v[(bRow + nxtBase + r) * H_ + c * 4]);
            }
            CP_COMMIT();
        }

        // ---- S = Q K^T  (S[m][n]: q row 8i+m, kv col 4j+n) ----
        float S[8][4];
#pragma unroll
        for (int m = 0; m < 8; m++)
#pragma unroll
            for (int n = 0; n < 4; n++) S[m][n] = 0.0f;

#pragma unroll 4
        for (int h4 = 0; h4 < 16; h4++) {
            float4 kf[4];
#pragma unroll
            for (int n = 0; n < 4; n++)
                kf[n] = *(const float4*)&Ks[(4 * j + n) * 64 + 4 * (h4 ^ j)];
#pragma unroll
            for (int m = 0; m < 8; m++) {
                float4 a = *(const float4*)&Qs[(8 * i + m) * 64 + 4 * h4];
#pragma unroll
                for (int n = 0; n < 4; n++) {
                    S[m][n] += a.x * kf[n].x;
                    S[m][n] += a.y * kf[n].y;
                    S[m][n] += a.z * kf[n].z;
                    S[m][n] += a.w * kf[n].w;
                }
            }
        }
        __syncthreads();   // K reads done; Ps (= Ks) may be overwritten

        // causal mask on the diagonal tile
        if (kt == qt) {
#pragma unroll
            for (int m = 0; m < 8; m++)
#pragma unroll
                for (int n = 0; n < 4; n++)
                    if (4 * j + n > 8 * i + m) S[m][n] = -1e30f;
        }

        // ---- online softmax; write P ----
#pragma unroll
        for (int m = 0; m < 8; m++) {
            float rmax = fmaxf(fmaxf(S[m][0], S[m][1]), fmaxf(S[m][2], S[m][3]));
#pragma unroll
            for (int msk = 8; msk >= 1; msk >>= 1)
                rmax = fmaxf(rmax, __shfl_xor_sync(0xffffffffu, rmax, msk));
            float mNew = fmaxf(m_i[m], rmax);
            float factor = exp2f(m_i[m] - mNew);
            float4 pv;
            pv.x = exp2f(S[m][0] - mNew);
            pv.y = exp2f(S[m][1] - mNew);
            pv.z = exp2f(S[m][2] - mNew);
            pv.w = exp2f(S[m][3] - mNew);
            float rsum = pv.x + pv.y + pv.z + pv.w;
#pragma unroll
            for (int msk = 8; msk >= 1; msk >>= 1)
                rsum += __shfl_xor_sync(0xffffffffu, rsum, msk);
            l_i[m] = l_i[m] * factor + rsum;
            m_i[m] = mNew;
            acc[m][0] *= factor; acc[m][1] *= factor;
            acc[m][2] *= factor; acc[m][3] *= factor;
            *(float4*)&Ps[(8 * i + m) * 64 + 4 * j] = pv;
        }
        __syncthreads();   // P visible

        // ---- O += P V  (acc[m][c]: q row 8i+m, h col 4j+c) ----
#pragma unroll 4
        for (int kv4 = 0; kv4 < 16; kv4++) {
            float4 vf[4];
#pragma unroll
            for (int n = 0; n < 4; n++)
                vf[n] = *(const float4*)&Vs[(4 * kv4 + n) * 64 + 4 * j];
#pragma unroll
            for (int m = 0; m < 8; m++) {
                float4 pm = *(const float4*)&Ps[(8 * i + m) * 64 + 4 * kv4];
                acc[m][0] += pm.x * vf[0].x; acc[m][0] += pm.y * vf[1].x;
                acc[m][0] += pm.z * vf[2].x; acc[m][0] += pm.w * vf[3].x;
                acc[m][1] += pm.x * vf[0].y; acc[m][1] += pm.y * vf[1].y;
                acc[m][1] += pm.z * vf[2].y; acc[m][1] += pm.w * vf[3].y;
                acc[m][2] += pm.x * vf[0].z; acc[m][2] += pm.y * vf[1].z;
                acc[m][2] += pm.z * vf[2].z; acc[m][2] += pm.w * vf[3].z;
                acc[m][3] += pm.x * vf[0].w; acc[m][3] += pm.y * vf[1].w;
                acc[m][3] += pm.z * vf[2].w; acc[m][3] += pm.w * vf[3].w;
            }
        }
        // no trailing sync: next iteration's top sync protects buffer reuse
    }

    // epilogue: normalize and store
#pragma unroll
    for (int m = 0; m < 8; m++) {
        float inv = 1.0f / l_i[m];
        float4 o;
        o.x = acc[m][0] * inv; o.y = acc[m][1] * inv;
        o.z = acc[m][2] * inv; o.w = acc[m][3] * inv;
        *(float4*)&out[(bRow + qBase + 8 * i + m) * H_ + 4 * j] = o;
    }
}

// ---------------------------------------------------------------------------
extern "C" void kernel_launch(void* const* d_in, const int* in_sizes, int n_in,
                              void* d_out, int out_size)
{
    const float* x  = (const float*)d_in[0];
    const float* wq = (const float*)d_in[1];
    const float* wk = (const float*)d_in[2];
    const float* wv = (const float*)d_in[3];
    float* out = (float*)d_out;

    cudaFuncSetAttribute(attn_kernel,
                         cudaFuncAttributeMaxDynamicSharedMemorySize, ATTN_SMEM);

    dim3 gProj(ROWS_ / 128, 3);
    qkv_proj_kernel<<<gProj, 256>>>(x, wq, wk, wv);
    attn_kernel<<<16 * 32, 128, ATTN_SMEM>>>(out);
}